// round 11
// baseline (speedup 1.0000x reference)
#include <cuda_runtime.h>
#include <cstdint>

#define NSTEPS 64
#define DD 16
#define THREADS 256
#define RPT 1
#define ROWS_PER_CTA (THREADS * RPT)            // 256 (divides 2^21 exactly)
#define WEIGHT_FLOATS (NSTEPS * DD * DD)        // 16384
#define SMEM_BYTES (WEIGHT_FLOATS * 4)          // 64 KB: W only

typedef unsigned long long u64;

// V lives in constant memory (64 KB), filled per-call with cudaMemcpyToSymbolAsync.
__constant__ float cV[WEIGHT_FLOATS];

// ---- packed f32x2 helpers (sm_103a) ----
__device__ __forceinline__ u64 pack2(float lo, float hi) {
    u64 r;
    asm("mov.b64 %0, {%1, %2};" : "=l"(r) : "f"(lo), "f"(hi));
    return r;
}
__device__ __forceinline__ void unpack2(u64 v, float& lo, float& hi) {
    asm("mov.b64 {%0, %1}, %2;" : "=f"(lo), "=f"(hi) : "l"(v));
}
__device__ __forceinline__ u64 fma2(u64 a, u64 b, u64 c) {
    u64 d;
    asm("fma.rn.f32x2 %0, %1, %2, %3;" : "=l"(d) : "l"(a), "l"(b), "l"(c));
    return d;
}
__device__ __forceinline__ u64 mul2(u64 a, u64 b) {
    u64 d;
    asm("mul.rn.f32x2 %0, %1, %2;" : "=l"(d) : "l"(a), "l"(b));
    return d;
}
__device__ __forceinline__ float rcp_fast(float x) {
    float r;
    asm("rcp.approx.ftz.f32 %0, %1;" : "=f"(r) : "f"(x));
    return r;
}
__device__ __forceinline__ float ex2_fast(float x) {
    float r;
    asm("ex2.approx.ftz.f32 %0, %1;" : "=f"(r) : "f"(x));
    return r;
}

// A&S 7.1.26 erf constants
#define ERF_P   0.3275911f
#define ERF_A1  0.254829592f
#define ERF_A2 -0.284496736f
#define ERF_A3  1.421413741f
#define ERF_A4 -1.453152027f
#define ERF_A5  1.061405429f
#define INV_SQRT2 0.70710678118654752440f
#define NEG_LOG2E -1.44269504088896340736f
#define ABS2_MASK 0x7fffffff7fffffffULL
// 0.5/64: folds the residual 1/NSTEPS scaling into GELU for free
#define HALF_INVN (0.5f / 64.0f)

// returns (gelu(x)/64, gelu(y)/64); erf via A&S 7.1.26  (R8 known-good codegen)
__device__ __forceinline__ u64 gelu2_scaled(u64 xy) {
    float x, y;
    unpack2(xy, x, y);
    float ax = fabsf(x) * INV_SQRT2;
    float ay = fabsf(y) * INV_SQRT2;
    float tx = rcp_fast(fmaf(ERF_P, ax, 1.0f));
    float ty = rcp_fast(fmaf(ERF_P, ay, 1.0f));
    float ex = ex2_fast(ax * ax * NEG_LOG2E);
    float ey = ex2_fast(ay * ay * NEG_LOG2E);
    u64 t2 = pack2(tx, ty);
    u64 e2 = pack2(ex, ey);
    u64 p = fma2(pack2(-ERF_A5, -ERF_A5), t2, pack2(-ERF_A4, -ERF_A4));
    p = fma2(p, t2, pack2(-ERF_A3, -ERF_A3));
    p = fma2(p, t2, pack2(-ERF_A2, -ERF_A2));
    p = fma2(p, t2, pack2(-ERF_A1, -ERF_A1));
    p = mul2(p, t2);
    u64 E2 = fma2(p, e2, pack2(1.0f, 1.0f));            // E = 1 - P(t)*e^{-z^2}
    u64 sc2 = pack2(HALF_INVN, HALF_INVN);
    u64 hx   = mul2(xy, sc2);                           // (0.5/64)*x
    u64 habs = hx & ABS2_MASK;                          // (0.5/64)*|x|
    return fma2(habs, E2, hx);                          // (x/2 + |x|/2*E)/64
}

__global__ __launch_bounds__(THREADS, 3)
void resnet_steps_kernel(const float* __restrict__ x,
                         const float* __restrict__ W,
                         float* __restrict__ out)
{
    extern __shared__ float smem[];   // [0,16384): W fp32
    const int tid = threadIdx.x;

    {
        const float4* Wg = reinterpret_cast<const float4*>(W);
        float4* sW4 = reinterpret_cast<float4*>(smem);
        for (int i = tid; i < WEIGHT_FLOATS / 4; i += THREADS)
            sW4[i] = Wg[i];
    }
    __syncthreads();

    const int base_row = blockIdx.x * ROWS_PER_CTA + tid;

    u64 h[RPT][8];
    #pragma unroll
    for (int r = 0; r < RPT; r++) {
        const float4* xr = reinterpret_cast<const float4*>(x) + (base_row + r * THREADS) * 4;
        #pragma unroll
        for (int q = 0; q < 4; q++) {
            float4 t = xr[q];
            h[r][2 * q]     = pack2(t.x, t.y);
            h[r][2 * q + 1] = pack2(t.z, t.w);
        }
    }

    const ulonglong2* sW = reinterpret_cast<const ulonglong2*>(smem);
    const ulonglong2* cVp = reinterpret_cast<const ulonglong2*>(cV);

    #pragma unroll 1
    for (int s = 0; s < NSTEPS; s++) {
        const ulonglong2* Ws = sW + s * (DD * DD / 4);    // 64 ulonglong2 per step
        const ulonglong2* Vs = cVp + s * (DD * DD / 4);

        // ---- g = h @ W_s  (W from shared memory, LDS.128 broadcast) ----
        u64 acc[RPT][8];
        #pragma unroll
        for (int r = 0; r < RPT; r++)
            #pragma unroll
            for (int i = 0; i < 8; i++) acc[r][i] = 0ULL;

        #pragma unroll 1
        for (int kp = 0; kp < 8; kp++) {
            ulonglong2 w0 = Ws[kp * 8 + 0];
            ulonglong2 w1 = Ws[kp * 8 + 1];
            ulonglong2 w2 = Ws[kp * 8 + 2];
            ulonglong2 w3 = Ws[kp * 8 + 3];
            ulonglong2 w4 = Ws[kp * 8 + 4];
            ulonglong2 w5 = Ws[kp * 8 + 5];
            ulonglong2 w6 = Ws[kp * 8 + 6];
            ulonglong2 w7 = Ws[kp * 8 + 7];
            #pragma unroll
            for (int r = 0; r < RPT; r++) {
                float a, b;
                unpack2(h[r][kp], a, b);
                const u64 ha = pack2(a, a);
                const u64 hb = pack2(b, b);
                acc[r][0] = fma2(ha, w0.x, acc[r][0]);
                acc[r][1] = fma2(ha, w0.y, acc[r][1]);
                acc[r][2] = fma2(ha, w1.x, acc[r][2]);
                acc[r][3] = fma2(ha, w1.y, acc[r][3]);
                acc[r][4] = fma2(ha, w2.x, acc[r][4]);
                acc[r][5] = fma2(ha, w2.y, acc[r][5]);
                acc[r][6] = fma2(ha, w3.x, acc[r][6]);
                acc[r][7] = fma2(ha, w3.y, acc[r][7]);
                acc[r][0] = fma2(hb, w4.x, acc[r][0]);
                acc[r][1] = fma2(hb, w4.y, acc[r][1]);
                acc[r][2] = fma2(hb, w5.x, acc[r][2]);
                acc[r][3] = fma2(hb, w5.y, acc[r][3]);
                acc[r][4] = fma2(hb, w6.x, acc[r][4]);
                acc[r][5] = fma2(hb, w6.y, acc[r][5]);
                acc[r][6] = fma2(hb, w7.x, acc[r][6]);
                acc[r][7] = fma2(hb, w7.y, acc[r][7]);
            }
        }

        // ---- h += (GELU(g)/64) @ V_s  (V from constant memory, LDC.128) ----
        #pragma unroll 1
        for (int kp = 0; kp < 8; kp++) {
            ulonglong2 v0 = Vs[kp * 8 + 0];
            ulonglong2 v1 = Vs[kp * 8 + 1];
            ulonglong2 v2 = Vs[kp * 8 + 2];
            ulonglong2 v3 = Vs[kp * 8 + 3];
            ulonglong2 v4 = Vs[kp * 8 + 4];
            ulonglong2 v5 = Vs[kp * 8 + 5];
            ulonglong2 v6 = Vs[kp * 8 + 6];
            ulonglong2 v7 = Vs[kp * 8 + 7];
            #pragma unroll
            for (int r = 0; r < RPT; r++) {
                u64 g2 = gelu2_scaled(acc[r][kp]);
                float a, b;
                unpack2(g2, a, b);
                const u64 ga = pack2(a, a);
                const u64 gb = pack2(b, b);
                h[r][0] = fma2(ga, v0.x, h[r][0]);
                h[r][1] = fma2(ga, v0.y, h[r][1]);
                h[r][2] = fma2(ga, v1.x, h[r][2]);
                h[r][3] = fma2(ga, v1.y, h[r][3]);
                h[r][4] = fma2(ga, v2.x, h[r][4]);
                h[r][5] = fma2(ga, v2.y, h[r][5]);
                h[r][6] = fma2(ga, v3.x, h[r][6]);
                h[r][7] = fma2(ga, v3.y, h[r][7]);
                h[r][0] = fma2(gb, v4.x, h[r][0]);
                h[r][1] = fma2(gb, v4.y, h[r][1]);
                h[r][2] = fma2(gb, v5.x, h[r][2]);
                h[r][3] = fma2(gb, v5.y, h[r][3]);
                h[r][4] = fma2(gb, v6.x, h[r][4]);
                h[r][5] = fma2(gb, v6.y, h[r][5]);
                h[r][6] = fma2(gb, v7.x, h[r][6]);
                h[r][7] = fma2(gb, v7.y, h[r][7]);
            }
        }
    }

    #pragma unroll
    for (int r = 0; r < RPT; r++) {
        float4* orow = reinterpret_cast<float4*>(out) + (base_row + r * THREADS) * 4;
        #pragma unroll
        for (int q = 0; q < 4; q++) {
            float4 t;
            unpack2(h[r][2 * q],     t.x, t.y);
            unpack2(h[r][2 * q + 1], t.z, t.w);
            orow[q] = t;
        }
    }
}

extern "C" void kernel_launch(void* const* d_in, const int* in_sizes, int n_in,
                              void* d_out, int out_size) {
    const float* x = (const float*)d_in[0];
    const float* W = (const float*)d_in[1];
    const float* V = (const float*)d_in[2];
    float* out = (float*)d_out;

    static bool attr_set = false;
    if (!attr_set) {
        cudaFuncSetAttribute(resnet_steps_kernel,
                             cudaFuncAttributeMaxDynamicSharedMemorySize, SMEM_BYTES);
        attr_set = true;
    }

    // V -> constant memory (device-to-device, graph-capturable memcpy node)
    cudaMemcpyToSymbolAsync(cV, V, WEIGHT_FLOATS * sizeof(float), 0,
                            cudaMemcpyDeviceToDevice);

    const long long batch = (long long)in_sizes[0] / DD;   // 2^21
    const int grid = (int)(batch / ROWS_PER_CTA);          // 8192, exact
    resnet_steps_kernel<<<grid, THREADS, SMEM_BYTES>>>(x, W, out);
}

// round 12
// speedup vs baseline: 1.4554x; 1.4554x over previous
#include <cuda_runtime.h>
#include <cstdint>

#define NSTEPS 64
#define DD 16
#define THREADS 288
#define RPT 2
#define ROWS_PER_CTA (THREADS * RPT)            // 576
#define WEIGHT_FLOATS (NSTEPS * DD * DD)        // 16384
#define SMEM_BYTES (WEIGHT_FLOATS * 4)          // 64 KB: W only

typedef unsigned long long u64;

// V lives in constant memory (64 KB), filled per-call with cudaMemcpyToSymbolAsync.
__constant__ float cV[WEIGHT_FLOATS];

// ---- packed f32x2 helpers (sm_103a) ----
__device__ __forceinline__ u64 pack2(float lo, float hi) {
    u64 r;
    asm("mov.b64 %0, {%1, %2};" : "=l"(r) : "f"(lo), "f"(hi));
    return r;
}
__device__ __forceinline__ void unpack2(u64 v, float& lo, float& hi) {
    asm("mov.b64 {%0, %1}, %2;" : "=f"(lo), "=f"(hi) : "l"(v));
}
__device__ __forceinline__ u64 fma2(u64 a, u64 b, u64 c) {
    u64 d;
    asm("fma.rn.f32x2 %0, %1, %2, %3;" : "=l"(d) : "l"(a), "l"(b), "l"(c));
    return d;
}
__device__ __forceinline__ u64 mul2(u64 a, u64 b) {
    u64 d;
    asm("mul.rn.f32x2 %0, %1, %2;" : "=l"(d) : "l"(a), "l"(b));
    return d;
}
__device__ __forceinline__ float rcp_fast(float x) {
    float r;
    asm("rcp.approx.ftz.f32 %0, %1;" : "=f"(r) : "f"(x));
    return r;
}
__device__ __forceinline__ float ex2_fast(float x) {
    float r;
    asm("ex2.approx.ftz.f32 %0, %1;" : "=f"(r) : "f"(x));
    return r;
}

// A&S 7.1.25 erf constants (degree-3, |err| <= 2.5e-5)
#define ERF_P   0.47047f
#define ERF_A1  0.3480242f
#define ERF_A2 -0.0958798f
#define ERF_A3  0.7478556f
#define INV_SQRT2 0.70710678118654752440f
#define NEG_LOG2E -1.44269504088896340736f
#define ABS2_MASK 0x7fffffff7fffffffULL
// 0.5/64: folds the residual 1/NSTEPS scaling into GELU for free
#define HALF_INVN (0.5f / 64.0f)

// returns (gelu(x)/64, gelu(y)/64); erf via A&S 7.1.25 (R8 codegen shape)
__device__ __forceinline__ u64 gelu2_scaled(u64 xy) {
    float x, y;
    unpack2(xy, x, y);
    float ax = fabsf(x) * INV_SQRT2;
    float ay = fabsf(y) * INV_SQRT2;
    float tx = rcp_fast(fmaf(ERF_P, ax, 1.0f));
    float ty = rcp_fast(fmaf(ERF_P, ay, 1.0f));
    float ex = ex2_fast(ax * ax * NEG_LOG2E);
    float ey = ex2_fast(ay * ay * NEG_LOG2E);
    u64 t2 = pack2(tx, ty);
    u64 e2 = pack2(ex, ey);
    // P = -(a3 t^3 + a2 t^2 + a1 t) via negated coefs (packed Horner)
    u64 p = fma2(pack2(-ERF_A3, -ERF_A3), t2, pack2(-ERF_A2, -ERF_A2));
    p = fma2(p, t2, pack2(-ERF_A1, -ERF_A1));
    p = mul2(p, t2);
    u64 E2 = fma2(p, e2, pack2(1.0f, 1.0f));            // E = 1 - P(t)*e^{-z^2}
    u64 sc2 = pack2(HALF_INVN, HALF_INVN);
    u64 hx   = mul2(xy, sc2);                           // (0.5/64)*x
    u64 habs = hx & ABS2_MASK;                          // (0.5/64)*|x|
    return fma2(habs, E2, hx);                          // (x/2 + |x|/2*E)/64
}

__global__ __launch_bounds__(THREADS, 2)
void resnet_steps_kernel(const float* __restrict__ x,
                         const float* __restrict__ W,
                         float* __restrict__ out,
                         int batch)
{
    extern __shared__ float smem[];   // [0,16384): W fp32
    const int tid = threadIdx.x;

    {
        const float4* Wg = reinterpret_cast<const float4*>(W);
        float4* sW4 = reinterpret_cast<float4*>(smem);
        for (int i = tid; i < WEIGHT_FLOATS / 4; i += THREADS)
            sW4[i] = Wg[i];
    }
    __syncthreads();

    const int base_row = blockIdx.x * ROWS_PER_CTA + tid;

    u64 h[RPT][8];
    #pragma unroll
    for (int r = 0; r < RPT; r++) {
        const int row = base_row + r * THREADS;
        if (row < batch) {
            const float4* xr = reinterpret_cast<const float4*>(x) + row * 4;
            #pragma unroll
            for (int q = 0; q < 4; q++) {
                float4 t = xr[q];
                h[r][2 * q]     = pack2(t.x, t.y);
                h[r][2 * q + 1] = pack2(t.z, t.w);
            }
        } else {
            #pragma unroll
            for (int i = 0; i < 8; i++) h[r][i] = 0ULL;
        }
    }

    const ulonglong2* sW = reinterpret_cast<const ulonglong2*>(smem);
    const ulonglong2* cVp = reinterpret_cast<const ulonglong2*>(cV);

    #pragma unroll 1
    for (int s = 0; s < NSTEPS; s++) {
        const ulonglong2* Ws = sW + s * (DD * DD / 4);    // 64 ulonglong2 per step
        const ulonglong2* Vs = cVp + s * (DD * DD / 4);

        // ---- g = h @ W_s  (W from shared memory, LDS.128 broadcast) ----
        u64 acc[RPT][8];
        #pragma unroll
        for (int r = 0; r < RPT; r++)
            #pragma unroll
            for (int i = 0; i < 8; i++) acc[r][i] = 0ULL;

        #pragma unroll 1
        for (int kp = 0; kp < 8; kp++) {
            ulonglong2 w0 = Ws[kp * 8 + 0];
            ulonglong2 w1 = Ws[kp * 8 + 1];
            ulonglong2 w2 = Ws[kp * 8 + 2];
            ulonglong2 w3 = Ws[kp * 8 + 3];
            ulonglong2 w4 = Ws[kp * 8 + 4];
            ulonglong2 w5 = Ws[kp * 8 + 5];
            ulonglong2 w6 = Ws[kp * 8 + 6];
            ulonglong2 w7 = Ws[kp * 8 + 7];
            #pragma unroll
            for (int r = 0; r < RPT; r++) {
                float a, b;
                unpack2(h[r][kp], a, b);
                const u64 ha = pack2(a, a);
                const u64 hb = pack2(b, b);
                acc[r][0] = fma2(ha, w0.x, acc[r][0]);
                acc[r][1] = fma2(ha, w0.y, acc[r][1]);
                acc[r][2] = fma2(ha, w1.x, acc[r][2]);
                acc[r][3] = fma2(ha, w1.y, acc[r][3]);
                acc[r][4] = fma2(ha, w2.x, acc[r][4]);
                acc[r][5] = fma2(ha, w2.y, acc[r][5]);
                acc[r][6] = fma2(ha, w3.x, acc[r][6]);
                acc[r][7] = fma2(ha, w3.y, acc[r][7]);
                acc[r][0] = fma2(hb, w4.x, acc[r][0]);
                acc[r][1] = fma2(hb, w4.y, acc[r][1]);
                acc[r][2] = fma2(hb, w5.x, acc[r][2]);
                acc[r][3] = fma2(hb, w5.y, acc[r][3]);
                acc[r][4] = fma2(hb, w6.x, acc[r][4]);
                acc[r][5] = fma2(hb, w6.y, acc[r][5]);
                acc[r][6] = fma2(hb, w7.x, acc[r][6]);
                acc[r][7] = fma2(hb, w7.y, acc[r][7]);
            }
        }

        // ---- h += (GELU(g)/64) @ V_s  (V from constant memory, LDC.128) ----
        #pragma unroll 1
        for (int kp = 0; kp < 8; kp++) {
            ulonglong2 v0 = Vs[kp * 8 + 0];
            ulonglong2 v1 = Vs[kp * 8 + 1];
            ulonglong2 v2 = Vs[kp * 8 + 2];
            ulonglong2 v3 = Vs[kp * 8 + 3];
            ulonglong2 v4 = Vs[kp * 8 + 4];
            ulonglong2 v5 = Vs[kp * 8 + 5];
            ulonglong2 v6 = Vs[kp * 8 + 6];
            ulonglong2 v7 = Vs[kp * 8 + 7];
            #pragma unroll
            for (int r = 0; r < RPT; r++) {
                u64 g2 = gelu2_scaled(acc[r][kp]);
                float a, b;
                unpack2(g2, a, b);
                const u64 ga = pack2(a, a);
                const u64 gb = pack2(b, b);
                h[r][0] = fma2(ga, v0.x, h[r][0]);
                h[r][1] = fma2(ga, v0.y, h[r][1]);
                h[r][2] = fma2(ga, v1.x, h[r][2]);
                h[r][3] = fma2(ga, v1.y, h[r][3]);
                h[r][4] = fma2(ga, v2.x, h[r][4]);
                h[r][5] = fma2(ga, v2.y, h[r][5]);
                h[r][6] = fma2(ga, v3.x, h[r][6]);
                h[r][7] = fma2(ga, v3.y, h[r][7]);
                h[r][0] = fma2(gb, v4.x, h[r][0]);
                h[r][1] = fma2(gb, v4.y, h[r][1]);
                h[r][2] = fma2(gb, v5.x, h[r][2]);
                h[r][3] = fma2(gb, v5.y, h[r][3]);
                h[r][4] = fma2(gb, v6.x, h[r][4]);
                h[r][5] = fma2(gb, v6.y, h[r][5]);
                h[r][6] = fma2(gb, v7.x, h[r][6]);
                h[r][7] = fma2(gb, v7.y, h[r][7]);
            }
        }
    }

    #pragma unroll
    for (int r = 0; r < RPT; r++) {
        const int row = base_row + r * THREADS;
        if (row < batch) {
            float4* orow = reinterpret_cast<float4*>(out) + row * 4;
            #pragma unroll
            for (int q = 0; q < 4; q++) {
                float4 t;
                unpack2(h[r][2 * q],     t.x, t.y);
                unpack2(h[r][2 * q + 1], t.z, t.w);
                orow[q] = t;
            }
        }
    }
}

extern "C" void kernel_launch(void* const* d_in, const int* in_sizes, int n_in,
                              void* d_out, int out_size) {
    const float* x = (const float*)d_in[0];
    const float* W = (const float*)d_in[1];
    const float* V = (const float*)d_in[2];
    float* out = (float*)d_out;

    static bool attr_set = false;
    if (!attr_set) {
        cudaFuncSetAttribute(resnet_steps_kernel,
                             cudaFuncAttributeMaxDynamicSharedMemorySize, SMEM_BYTES);
        attr_set = true;
    }

    // V -> constant memory (device-to-device, graph-capturable memcpy node)
    cudaMemcpyToSymbolAsync(cV, V, WEIGHT_FLOATS * sizeof(float), 0,
                            cudaMemcpyDeviceToDevice);

    const int batch = in_sizes[0] / DD;                        // 2^21
    const int grid = (batch + ROWS_PER_CTA - 1) / ROWS_PER_CTA; // 3641
    resnet_steps_kernel<<<grid, THREADS, SMEM_BYTES>>>(x, W, out, batch);
}

// round 13
// speedup vs baseline: 1.6227x; 1.1149x over previous
#include <cuda_runtime.h>
#include <cstdint>

#define NSTEPS 64
#define DD 16
#define THREADS 256
#define RPT 2
#define ROWS_PER_CTA (THREADS * RPT)            // 512 (divides 2^21 exactly)
#define WEIGHT_FLOATS (NSTEPS * DD * DD)        // 16384
#define SMEM_BYTES (WEIGHT_FLOATS * 4)          // 64 KB: W only

typedef unsigned long long u64;

// V lives in constant memory (64 KB), filled per-call with cudaMemcpyToSymbolAsync.
__constant__ float cV[WEIGHT_FLOATS];

// ---- packed f32x2 helpers (sm_103a) ----
__device__ __forceinline__ u64 pack2(float lo, float hi) {
    u64 r;
    asm("mov.b64 %0, {%1, %2};" : "=l"(r) : "f"(lo), "f"(hi));
    return r;
}
__device__ __forceinline__ void unpack2(u64 v, float& lo, float& hi) {
    asm("mov.b64 {%0, %1}, %2;" : "=f"(lo), "=f"(hi) : "l"(v));
}
__device__ __forceinline__ u64 fma2(u64 a, u64 b, u64 c) {
    u64 d;
    asm("fma.rn.f32x2 %0, %1, %2, %3;" : "=l"(d) : "l"(a), "l"(b), "l"(c));
    return d;
}
__device__ __forceinline__ u64 mul2(u64 a, u64 b) {
    u64 d;
    asm("mul.rn.f32x2 %0, %1, %2;" : "=l"(d) : "l"(a), "l"(b));
    return d;
}
__device__ __forceinline__ float rcp_fast(float x) {
    float r;
    asm("rcp.approx.ftz.f32 %0, %1;" : "=f"(r) : "f"(x));
    return r;
}
__device__ __forceinline__ float ex2_fast(float x) {
    float r;
    asm("ex2.approx.ftz.f32 %0, %1;" : "=f"(r) : "f"(x));
    return r;
}

// tanh-GELU constants: gelu(x) = 0.5x(1+tanh(s(x+0.044715x^3))), s=sqrt(2/pi)
// tanh(z) = 1 - 2/(e^{2z}+1); compute m = 2z*log2(e) = x*(Q1 + Q2*x^2)
#define GELU_Q1 2.3022585093f           // 2*s*log2(e)
#define GELU_Q2 0.1029445705f           // 2*s*log2(e)*0.044715
#define INVN_F  (1.0f / 64.0f)          // folds residual 1/NSTEPS scaling

// returns (gelu(x)/64, gelu(y)/64) via tanh form; 7 fma-pipe ops + 4 MUFU
__device__ __forceinline__ u64 gelu2_scaled(u64 xy) {
    const u64 one2 = pack2(1.0f, 1.0f);
    u64 u = mul2(xy, xy);                            // x^2
    u64 w = fma2(u, pack2(GELU_Q2, GELU_Q2),
                    pack2(GELU_Q1, GELU_Q1));        // Q1 + Q2*x^2
    u64 m = mul2(xy, w);                             // 2z*log2(e)
    float m_l, m_h;
    unpack2(m, m_l, m_h);
    u64 e2 = pack2(ex2_fast(m_l), ex2_fast(m_h));    // e^{2z}
    u64 t  = fma2(e2, one2, one2);                   // e^{2z} + 1
    float t_l, t_h;
    unpack2(t, t_l, t_h);
    u64 r2 = pack2(rcp_fast(t_l), rcp_fast(t_h));    // r = 1/(e^{2z}+1)
    u64 nr = fma2(r2, pack2(-1.0f, -1.0f), one2);    // 1 - r
    u64 hx = mul2(xy, pack2(INVN_F, INVN_F));        // x/64
    return mul2(hx, nr);                             // x*(1-r)/64 = gelu(x)/64
}

__global__ __launch_bounds__(THREADS, 2)
void resnet_steps_kernel(const float* __restrict__ x,
                         const float* __restrict__ W,
                         float* __restrict__ out)
{
    extern __shared__ float smem[];   // [0,16384): W fp32
    const int tid = threadIdx.x;

    {
        const float4* Wg = reinterpret_cast<const float4*>(W);
        float4* sW4 = reinterpret_cast<float4*>(smem);
        for (int i = tid; i < WEIGHT_FLOATS / 4; i += THREADS)
            sW4[i] = Wg[i];
    }
    __syncthreads();

    const int base_row = blockIdx.x * ROWS_PER_CTA + tid;

    u64 h[RPT][8];
    #pragma unroll
    for (int r = 0; r < RPT; r++) {
        const float4* xr = reinterpret_cast<const float4*>(x) + (base_row + r * THREADS) * 4;
        #pragma unroll
        for (int q = 0; q < 4; q++) {
            float4 t = xr[q];
            h[r][2 * q]     = pack2(t.x, t.y);
            h[r][2 * q + 1] = pack2(t.z, t.w);
        }
    }

    const ulonglong2* sW = reinterpret_cast<const ulonglong2*>(smem);
    const ulonglong2* cVp = reinterpret_cast<const ulonglong2*>(cV);

    #pragma unroll 1
    for (int s = 0; s < NSTEPS; s++) {
        const ulonglong2* Ws = sW + s * (DD * DD / 4);    // 64 ulonglong2 per step
        const ulonglong2* Vs = cVp + s * (DD * DD / 4);

        // ---- g = h @ W_s  (W from shared memory, LDS.128 broadcast) ----
        u64 acc[RPT][8];
        #pragma unroll
        for (int r = 0; r < RPT; r++)
            #pragma unroll
            for (int i = 0; i < 8; i++) acc[r][i] = 0ULL;

        #pragma unroll 1
        for (int kp = 0; kp < 8; kp++) {
            ulonglong2 w0 = Ws[kp * 8 + 0];
            ulonglong2 w1 = Ws[kp * 8 + 1];
            ulonglong2 w2 = Ws[kp * 8 + 2];
            ulonglong2 w3 = Ws[kp * 8 + 3];
            ulonglong2 w4 = Ws[kp * 8 + 4];
            ulonglong2 w5 = Ws[kp * 8 + 5];
            ulonglong2 w6 = Ws[kp * 8 + 6];
            ulonglong2 w7 = Ws[kp * 8 + 7];
            #pragma unroll
            for (int r = 0; r < RPT; r++) {
                float a, b;
                unpack2(h[r][kp], a, b);
                const u64 ha = pack2(a, a);
                const u64 hb = pack2(b, b);
                acc[r][0] = fma2(ha, w0.x, acc[r][0]);
                acc[r][1] = fma2(ha, w0.y, acc[r][1]);
                acc[r][2] = fma2(ha, w1.x, acc[r][2]);
                acc[r][3] = fma2(ha, w1.y, acc[r][3]);
                acc[r][4] = fma2(ha, w2.x, acc[r][4]);
                acc[r][5] = fma2(ha, w2.y, acc[r][5]);
                acc[r][6] = fma2(ha, w3.x, acc[r][6]);
                acc[r][7] = fma2(ha, w3.y, acc[r][7]);
                acc[r][0] = fma2(hb, w4.x, acc[r][0]);
                acc[r][1] = fma2(hb, w4.y, acc[r][1]);
                acc[r][2] = fma2(hb, w5.x, acc[r][2]);
                acc[r][3] = fma2(hb, w5.y, acc[r][3]);
                acc[r][4] = fma2(hb, w6.x, acc[r][4]);
                acc[r][5] = fma2(hb, w6.y, acc[r][5]);
                acc[r][6] = fma2(hb, w7.x, acc[r][6]);
                acc[r][7] = fma2(hb, w7.y, acc[r][7]);
            }
        }

        // ---- h += (GELU(g)/64) @ V_s  (V from constant memory, LDC.128) ----
        #pragma unroll 1
        for (int kp = 0; kp < 8; kp++) {
            ulonglong2 v0 = Vs[kp * 8 + 0];
            ulonglong2 v1 = Vs[kp * 8 + 1];
            ulonglong2 v2 = Vs[kp * 8 + 2];
            ulonglong2 v3 = Vs[kp * 8 + 3];
            ulonglong2 v4 = Vs[kp * 8 + 4];
            ulonglong2 v5 = Vs[kp * 8 + 5];
            ulonglong2 v6 = Vs[kp * 8 + 6];
            ulonglong2 v7 = Vs[kp * 8 + 7];
            #pragma unroll
            for (int r = 0; r < RPT; r++) {
                u64 g2 = gelu2_scaled(acc[r][kp]);
                float a, b;
                unpack2(g2, a, b);
                const u64 ga = pack2(a, a);
                const u64 gb = pack2(b, b);
                h[r][0] = fma2(ga, v0.x, h[r][0]);
                h[r][1] = fma2(ga, v0.y, h[r][1]);
                h[r][2] = fma2(ga, v1.x, h[r][2]);
                h[r][3] = fma2(ga, v1.y, h[r][3]);
                h[r][4] = fma2(ga, v2.x, h[r][4]);
                h[r][5] = fma2(ga, v2.y, h[r][5]);
                h[r][6] = fma2(ga, v3.x, h[r][6]);
                h[r][7] = fma2(ga, v3.y, h[r][7]);
                h[r][0] = fma2(gb, v4.x, h[r][0]);
                h[r][1] = fma2(gb, v4.y, h[r][1]);
                h[r][2] = fma2(gb, v5.x, h[r][2]);
                h[r][3] = fma2(gb, v5.y, h[r][3]);
                h[r][4] = fma2(gb, v6.x, h[r][4]);
                h[r][5] = fma2(gb, v6.y, h[r][5]);
                h[r][6] = fma2(gb, v7.x, h[r][6]);
                h[r][7] = fma2(gb, v7.y, h[r][7]);
            }
        }
    }

    #pragma unroll
    for (int r = 0; r < RPT; r++) {
        float4* orow = reinterpret_cast<float4*>(out) + (base_row + r * THREADS) * 4;
        #pragma unroll
        for (int q = 0; q < 4; q++) {
            float4 t;
            unpack2(h[r][2 * q],     t.x, t.y);
            unpack2(h[r][2 * q + 1], t.z, t.w);
            orow[q] = t;
        }
    }
}

extern "C" void kernel_launch(void* const* d_in, const int* in_sizes, int n_in,
                              void* d_out, int out_size) {
    const float* x = (const float*)d_in[0];
    const float* W = (const float*)d_in[1];
    const float* V = (const float*)d_in[2];
    float* out = (float*)d_out;

    static bool attr_set = false;
    if (!attr_set) {
        cudaFuncSetAttribute(resnet_steps_kernel,
                             cudaFuncAttributeMaxDynamicSharedMemorySize, SMEM_BYTES);
        attr_set = true;
    }

    // V -> constant memory (device-to-device, graph-capturable memcpy node)
    cudaMemcpyToSymbolAsync(cV, V, WEIGHT_FLOATS * sizeof(float), 0,
                            cudaMemcpyDeviceToDevice);

    const long long batch = (long long)in_sizes[0] / DD;   // 2^21
    const int grid = (int)(batch / ROWS_PER_CTA);          // 4096, exact
    resnet_steps_kernel<<<grid, THREADS, SMEM_BYTES>>>(x, W, out);
}

// round 14
// speedup vs baseline: 6.3418x; 3.9082x over previous
#include <cuda_runtime.h>
#include <cuda_bf16.h>
#include <cstdint>

#define NSTEPS 64
#define DD 16
#define THREADS 256
#define WARPS (THREADS / 32)
#define ROWS_PER_WARP 64
#define ROWS_PER_CTA (WARPS * ROWS_PER_WARP)    // 512 (divides 2^21 exactly)
#define WEIGHT_VALS (NSTEPS * DD * DD)          // 16384 per tensor
// smem: WT bf16 (32KB) + VT bf16 (32KB) = 64KB, both transposed [n][k] per step
#define SMEM_BYTES (2 * WEIGHT_VALS * 2)

typedef unsigned long long u64;
typedef unsigned int u32;

// ---- packed f32x2 helpers ----
__device__ __forceinline__ u64 pack2(float lo, float hi) {
    u64 r;
    asm("mov.b64 %0, {%1, %2};" : "=l"(r) : "f"(lo), "f"(hi));
    return r;
}
__device__ __forceinline__ void unpack2(u64 v, float& lo, float& hi) {
    asm("mov.b64 {%0, %1}, %2;" : "=f"(lo), "=f"(hi) : "l"(v));
}
__device__ __forceinline__ u64 fma2(u64 a, u64 b, u64 c) {
    u64 d;
    asm("fma.rn.f32x2 %0, %1, %2, %3;" : "=l"(d) : "l"(a), "l"(b), "l"(c));
    return d;
}
__device__ __forceinline__ u64 mul2(u64 a, u64 b) {
    u64 d;
    asm("mul.rn.f32x2 %0, %1, %2;" : "=l"(d) : "l"(a), "l"(b));
    return d;
}
__device__ __forceinline__ float rcp_fast(float x) {
    float r;
    asm("rcp.approx.ftz.f32 %0, %1;" : "=f"(r) : "f"(x));
    return r;
}
__device__ __forceinline__ float ex2_fast(float x) {
    float r;
    asm("ex2.approx.ftz.f32 %0, %1;" : "=f"(r) : "f"(x));
    return r;
}
// (lo, hi) -> bf16x2 register, lo in low 16 bits (convention verified in R7)
__device__ __forceinline__ u32 to_bf16x2(float lo, float hi) {
    u32 r;
    asm("cvt.rn.bf16x2.f32 %0, %1, %2;" : "=r"(r) : "f"(hi), "f"(lo));
    return r;
}

// m16n8k16 bf16 mma, f32 accumulate. A row-major, B col-major.
__device__ __forceinline__ void mma_bf16(
    float& d0, float& d1, float& d2, float& d3,
    u32 a0, u32 a1, u32 a2, u32 a3, u32 b0, u32 b1,
    float c0, float c1, float c2, float c3)
{
    asm("mma.sync.aligned.m16n8k16.row.col.f32.bf16.bf16.f32 "
        "{%0,%1,%2,%3}, {%4,%5,%6,%7}, {%8,%9}, {%10,%11,%12,%13};"
        : "=f"(d0), "=f"(d1), "=f"(d2), "=f"(d3)
        : "r"(a0), "r"(a1), "r"(a2), "r"(a3), "r"(b0), "r"(b1),
          "f"(c0), "f"(c1), "f"(c2), "f"(c3));
}

// tanh-GELU on a pair (plain gelu; the 1/64 residual scale is folded into V)
#define GELU_Q1 2.3022585093f           // 2*sqrt(2/pi)*log2(e)
#define GELU_Q2 0.1029445705f           // GELU_Q1 * 0.044715
__device__ __forceinline__ void gelu_pair(float x, float y, float& gx, float& gy) {
    const u64 one2 = pack2(1.0f, 1.0f);
    u64 xy = pack2(x, y);
    u64 u = mul2(xy, xy);                                   // x^2
    u64 w = fma2(u, pack2(GELU_Q2, GELU_Q2), pack2(GELU_Q1, GELU_Q1));
    u64 m = mul2(xy, w);                                    // 2z*log2(e)
    float ml, mh;
    unpack2(m, ml, mh);
    u64 e2 = pack2(ex2_fast(ml), ex2_fast(mh));             // e^{2z}
    u64 t = fma2(e2, one2, one2);                           // e^{2z}+1
    float tl, th;
    unpack2(t, tl, th);
    u64 r2 = pack2(rcp_fast(tl), rcp_fast(th));             // r
    u64 nr = fma2(r2, pack2(-1.0f, -1.0f), one2);           // 1-r = 0.5(1+tanh)
    u64 g = mul2(xy, nr);                                   // gelu(x)
    unpack2(g, gx, gy);
}

__global__ __launch_bounds__(THREADS, 2)
void resnet_steps_kernel(const float* __restrict__ x,
                         const float* __restrict__ W,
                         const float* __restrict__ V,
                         float* __restrict__ out)
{
    extern __shared__ __nv_bfloat16 sbf[];  // [0,16384): W^T ; [16384,32768): (V/64)^T
    const int tid = threadIdx.x;

    // Fill smem: per step s, store transposed [n][k] bf16. V pre-scaled by 1/64.
    {
        const float invn = 1.0f / (float)NSTEPS;
        for (int i = tid; i < WEIGHT_VALS; i += THREADS) {
            int s = i >> 8;
            int rem = i & 255;
            int k = rem >> 4;
            int n = rem & 15;
            int tidx = s * 256 + n * 16 + k;
            sbf[tidx] = __float2bfloat16(W[i]);                 // W[s][k][n]
            sbf[WEIGHT_VALS + tidx] = __float2bfloat16(V[i] * invn);
        }
    }
    __syncthreads();

    const int warp = tid >> 5;
    const int lane = tid & 31;
    const int gid = lane >> 2;    // groupID 0..7
    const int tig = lane & 3;     // thread-in-group 0..3

    const int rbase = blockIdx.x * ROWS_PER_CTA + warp * ROWS_PER_WARP;

    // h fragments: h[mt][nt][4] f32 — D-layout of m16n8 tiles.
    // c0=[gid][2tig], c1=[gid][2tig+1], c2=[gid+8][2tig], c3=[gid+8][2tig+1]
    float h[4][2][4];
    #pragma unroll
    for (int mt = 0; mt < 4; mt++) {
        #pragma unroll
        for (int nt = 0; nt < 2; nt++) {
            int row0 = rbase + mt * 16 + gid;
            int col = nt * 8 + tig * 2;
            float2 v0 = *reinterpret_cast<const float2*>(x + row0 * DD + col);
            float2 v1 = *reinterpret_cast<const float2*>(x + (row0 + 8) * DD + col);
            h[mt][nt][0] = v0.x; h[mt][nt][1] = v0.y;
            h[mt][nt][2] = v1.x; h[mt][nt][3] = v1.y;
        }
    }

    const u32* wt = reinterpret_cast<const u32*>(sbf);                    // 8192 u32
    const u32* vt = reinterpret_cast<const u32*>(sbf) + WEIGHT_VALS / 2;

    #pragma unroll 1
    for (int s = 0; s < NSTEPS; s++) {
        // B fragments from transposed bf16 weights: 8 conflict-free LDS.32.
        // b reg (nt, kk): u32 idx = s*128 + (8nt+gid)*8 + tig + 4kk
        int bidx = s * 128 + gid * 8 + tig;
        u32 bw00 = wt[bidx];        // nt0, k 2tig..+1
        u32 bw01 = wt[bidx + 4];    // nt0, k 2tig+8..
        u32 bw10 = wt[bidx + 64];   // nt1
        u32 bw11 = wt[bidx + 68];
        u32 bv00 = vt[bidx];
        u32 bv01 = vt[bidx + 4];
        u32 bv10 = vt[bidx + 64];
        u32 bv11 = vt[bidx + 68];

        #pragma unroll
        for (int mt = 0; mt < 4; mt++) {
            // A fragment of h (m16k16): lane-local cvt from D-layout (k-cols = n-cols)
            u32 a0 = to_bf16x2(h[mt][0][0], h[mt][0][1]);
            u32 a1 = to_bf16x2(h[mt][0][2], h[mt][0][3]);
            u32 a2 = to_bf16x2(h[mt][1][0], h[mt][1][1]);
            u32 a3 = to_bf16x2(h[mt][1][2], h[mt][1][3]);

            // g = h @ W_s  (two n-tiles)
            float g00, g01, g02, g03, g10, g11, g12, g13;
            mma_bf16(g00, g01, g02, g03, a0, a1, a2, a3, bw00, bw01,
                     0.0f, 0.0f, 0.0f, 0.0f);
            mma_bf16(g10, g11, g12, g13, a0, a1, a2, a3, bw10, bw11,
                     0.0f, 0.0f, 0.0f, 0.0f);

            // gelu elementwise on D-layout pairs
            float p00, p01, p02, p03, p10, p11, p12, p13;
            gelu_pair(g00, g01, p00, p01);
            gelu_pair(g02, g03, p02, p03);
            gelu_pair(g10, g11, p10, p11);
            gelu_pair(g12, g13, p12, p13);

            // A fragment of gelu(g) (lane-local again)
            u32 e0 = to_bf16x2(p00, p01);
            u32 e1 = to_bf16x2(p02, p03);
            u32 e2 = to_bf16x2(p10, p11);
            u32 e3 = to_bf16x2(p12, p13);

            // h += gelu(g) @ (V_s/64)  — C-accumulate is the residual add
            mma_bf16(h[mt][0][0], h[mt][0][1], h[mt][0][2], h[mt][0][3],
                     e0, e1, e2, e3, bv00, bv01,
                     h[mt][0][0], h[mt][0][1], h[mt][0][2], h[mt][0][3]);
            mma_bf16(h[mt][1][0], h[mt][1][1], h[mt][1][2], h[mt][1][3],
                     e0, e1, e2, e3, bv10, bv11,
                     h[mt][1][0], h[mt][1][1], h[mt][1][2], h[mt][1][3]);
        }
    }

    // Store h fragments
    #pragma unroll
    for (int mt = 0; mt < 4; mt++) {
        #pragma unroll
        for (int nt = 0; nt < 2; nt++) {
            int row0 = rbase + mt * 16 + gid;
            int col = nt * 8 + tig * 2;
            float2 v0 = make_float2(h[mt][nt][0], h[mt][nt][1]);
            float2 v1 = make_float2(h[mt][nt][2], h[mt][nt][3]);
            *reinterpret_cast<float2*>(out + row0 * DD + col) = v0;
            *reinterpret_cast<float2*>(out + (row0 + 8) * DD + col) = v1;
        }
    }
}

extern "C" void kernel_launch(void* const* d_in, const int* in_sizes, int n_in,
                              void* d_out, int out_size) {
    const float* x = (const float*)d_in[0];
    const float* W = (const float*)d_in[1];
    const float* V = (const float*)d_in[2];
    float* out = (float*)d_out;

    static bool attr_set = false;
    if (!attr_set) {
        cudaFuncSetAttribute(resnet_steps_kernel,
                             cudaFuncAttributeMaxDynamicSharedMemorySize, SMEM_BYTES);
        attr_set = true;
    }

    const long long batch = (long long)in_sizes[0] / DD;   // 2^21
    const int grid = (int)(batch / ROWS_PER_CTA);          // 4096, exact
    resnet_steps_kernel<<<grid, THREADS, SMEM_BYTES>>>(x, W, V, out);
}

// round 15
// speedup vs baseline: 8.7687x; 1.3827x over previous
#include <cuda_runtime.h>
#include <cuda_bf16.h>
#include <cstdint>

#define NSTEPS 64
#define DD 16
#define THREADS 256
#define WARPS (THREADS / 32)
#define ROWS_PER_WARP 64
#define ROWS_PER_CTA (WARPS * ROWS_PER_WARP)    // 512 (divides 2^21 exactly)
#define WEIGHT_VALS (NSTEPS * DD * DD)          // 16384 per tensor
// smem: WT bf16 (32KB) + VT bf16 (32KB) = 64KB, both transposed [n][k] per step
#define SMEM_BYTES (2 * WEIGHT_VALS * 2)

typedef unsigned long long u64;
typedef unsigned int u32;

// ---- packed f32x2 helpers ----
__device__ __forceinline__ u64 pack2(float lo, float hi) {
    u64 r;
    asm("mov.b64 %0, {%1, %2};" : "=l"(r) : "f"(lo), "f"(hi));
    return r;
}
__device__ __forceinline__ void unpack2(u64 v, float& lo, float& hi) {
    asm("mov.b64 {%0, %1}, %2;" : "=f"(lo), "=f"(hi) : "l"(v));
}
__device__ __forceinline__ u64 fma2(u64 a, u64 b, u64 c) {
    u64 d;
    asm("fma.rn.f32x2 %0, %1, %2, %3;" : "=l"(d) : "l"(a), "l"(b), "l"(c));
    return d;
}
__device__ __forceinline__ u64 mul2(u64 a, u64 b) {
    u64 d;
    asm("mul.rn.f32x2 %0, %1, %2;" : "=l"(d) : "l"(a), "l"(b));
    return d;
}
__device__ __forceinline__ float tanh_fast(float x) {
    float r;
    asm("tanh.approx.f32 %0, %1;" : "=f"(r) : "f"(x));
    return r;
}
// (lo, hi) -> bf16x2 register, lo in low 16 bits (convention verified in R7)
__device__ __forceinline__ u32 to_bf16x2(float lo, float hi) {
    u32 r;
    asm("cvt.rn.bf16x2.f32 %0, %1, %2;" : "=r"(r) : "f"(hi), "f"(lo));
    return r;
}

// m16n8k16 bf16 mma, f32 accumulate. A row-major, B col-major.
__device__ __forceinline__ void mma_bf16(
    float& d0, float& d1, float& d2, float& d3,
    u32 a0, u32 a1, u32 a2, u32 a3, u32 b0, u32 b1,
    float c0, float c1, float c2, float c3)
{
    asm("mma.sync.aligned.m16n8k16.row.col.f32.bf16.bf16.f32 "
        "{%0,%1,%2,%3}, {%4,%5,%6,%7}, {%8,%9}, {%10,%11,%12,%13};"
        : "=f"(d0), "=f"(d1), "=f"(d2), "=f"(d3)
        : "r"(a0), "r"(a1), "r"(a2), "r"(a3), "r"(b0), "r"(b1),
          "f"(c0), "f"(c1), "f"(c2), "f"(c3));
}

// tanh-GELU using MUFU.TANH: 5 fma-pipe ops + 2 MUFU per pair.
// gelu(x) = 0.5x(1 + tanh(x*(T1 + T2*x^2))), T1=sqrt(2/pi), T2=T1*0.044715
#define GELU_T1 0.7978845608f
#define GELU_T2 0.0356774081f
__device__ __forceinline__ void gelu_pair(float x, float y, float& gx, float& gy) {
    u64 xy = pack2(x, y);
    u64 u = mul2(xy, xy);                                   // x^2
    u64 w = fma2(u, pack2(GELU_T2, GELU_T2), pack2(GELU_T1, GELU_T1));
    u64 z = mul2(xy, w);                                    // tanh argument
    float zl, zh;
    unpack2(z, zl, zh);
    u64 t2 = pack2(tanh_fast(zl), tanh_fast(zh));           // tanh(z)
    u64 hx = mul2(xy, pack2(0.5f, 0.5f));                   // 0.5x
    u64 g = fma2(hx, t2, hx);                               // 0.5x(1+tanh)
    unpack2(g, gx, gy);
}

__global__ __launch_bounds__(THREADS, 2)
void resnet_steps_kernel(const float* __restrict__ x,
                         const float* __restrict__ W,
                         const float* __restrict__ V,
                         float* __restrict__ out)
{
    extern __shared__ __nv_bfloat16 sbf[];  // [0,16384): W^T ; [16384,32768): (V/64)^T
    const int tid = threadIdx.x;

    // Fill smem: per step s, store transposed [n][k] bf16. V pre-scaled by 1/64.
    {
        const float invn = 1.0f / (float)NSTEPS;
        for (int i = tid; i < WEIGHT_VALS; i += THREADS) {
            int s = i >> 8;
            int rem = i & 255;
            int k = rem >> 4;
            int n = rem & 15;
            int tidx = s * 256 + n * 16 + k;
            sbf[tidx] = __float2bfloat16(W[i]);                 // W[s][k][n]
            sbf[WEIGHT_VALS + tidx] = __float2bfloat16(V[i] * invn);
        }
    }
    __syncthreads();

    const int warp = tid >> 5;
    const int lane = tid & 31;
    const int gid = lane >> 2;    // groupID 0..7
    const int tig = lane & 3;     // thread-in-group 0..3

    const int rbase = blockIdx.x * ROWS_PER_CTA + warp * ROWS_PER_WARP;

    // h fragments: h[mt][nt][4] f32 — D-layout of m16n8 tiles.
    // c0=[gid][2tig], c1=[gid][2tig+1], c2=[gid+8][2tig], c3=[gid+8][2tig+1]
    float h[4][2][4];
    #pragma unroll
    for (int mt = 0; mt < 4; mt++) {
        #pragma unroll
        for (int nt = 0; nt < 2; nt++) {
            int row0 = rbase + mt * 16 + gid;
            int col = nt * 8 + tig * 2;
            float2 v0 = *reinterpret_cast<const float2*>(x + row0 * DD + col);
            float2 v1 = *reinterpret_cast<const float2*>(x + (row0 + 8) * DD + col);
            h[mt][nt][0] = v0.x; h[mt][nt][1] = v0.y;
            h[mt][nt][2] = v1.x; h[mt][nt][3] = v1.y;
        }
    }

    const u32* wt = reinterpret_cast<const u32*>(sbf);                    // 8192 u32
    const u32* vt = reinterpret_cast<const u32*>(sbf) + WEIGHT_VALS / 2;

    #pragma unroll 1
    for (int s = 0; s < NSTEPS; s++) {
        // B fragments from transposed bf16 weights: 8 conflict-free LDS.32.
        // b reg (nt, kk): u32 idx = s*128 + (8nt+gid)*8 + tig + 4kk
        int bidx = s * 128 + gid * 8 + tig;
        u32 bw00 = wt[bidx];        // nt0, k 2tig..+1
        u32 bw01 = wt[bidx + 4];    // nt0, k 2tig+8..
        u32 bw10 = wt[bidx + 64];   // nt1
        u32 bw11 = wt[bidx + 68];
        u32 bv00 = vt[bidx];
        u32 bv01 = vt[bidx + 4];
        u32 bv10 = vt[bidx + 64];
        u32 bv11 = vt[bidx + 68];

        #pragma unroll
        for (int mt = 0; mt < 4; mt++) {
            // A fragment of h (m16k16): lane-local cvt from D-layout (k-cols = n-cols)
            u32 a0 = to_bf16x2(h[mt][0][0], h[mt][0][1]);
            u32 a1 = to_bf16x2(h[mt][0][2], h[mt][0][3]);
            u32 a2 = to_bf16x2(h[mt][1][0], h[mt][1][1]);
            u32 a3 = to_bf16x2(h[mt][1][2], h[mt][1][3]);

            // g = h @ W_s  (two n-tiles)
            float g00, g01, g02, g03, g10, g11, g12, g13;
            mma_bf16(g00, g01, g02, g03, a0, a1, a2, a3, bw00, bw01,
                     0.0f, 0.0f, 0.0f, 0.0f);
            mma_bf16(g10, g11, g12, g13, a0, a1, a2, a3, bw10, bw11,
                     0.0f, 0.0f, 0.0f, 0.0f);

            // gelu elementwise on D-layout pairs
            float p00, p01, p02, p03, p10, p11, p12, p13;
            gelu_pair(g00, g01, p00, p01);
            gelu_pair(g02, g03, p02, p03);
            gelu_pair(g10, g11, p10, p11);
            gelu_pair(g12, g13, p12, p13);

            // A fragment of gelu(g) (lane-local again)
            u32 e0 = to_bf16x2(p00, p01);
            u32 e1 = to_bf16x2(p02, p03);
            u32 e2 = to_bf16x2(p10, p11);
            u32 e3 = to_bf16x2(p12, p13);

            // h += gelu(g) @ (V_s/64)  — C-accumulate is the residual add
            mma_bf16(h[mt][0][0], h[mt][0][1], h[mt][0][2], h[mt][0][3],
                     e0, e1, e2, e3, bv00, bv01,
                     h[mt][0][0], h[mt][0][1], h[mt][0][2], h[mt][0][3]);
            mma_bf16(h[mt][1][0], h[mt][1][1], h[mt][1][2], h[mt][1][3],
                     e0, e1, e2, e3, bv10, bv11,
                     h[mt][1][0], h[mt][1][1], h[mt][1][2], h[mt][1][3]);
        }
    }

    // Store h fragments
    #pragma unroll
    for (int mt = 0; mt < 4; mt++) {
        #pragma unroll
        for (int nt = 0; nt < 2; nt++) {
            int row0 = rbase + mt * 16 + gid;
            int col = nt * 8 + tig * 2;
            float2 v0 = make_float2(h[mt][nt][0], h[mt][nt][1]);
            float2 v1 = make_float2(h[mt][nt][2], h[mt][nt][3]);
            *reinterpret_cast<float2*>(out + row0 * DD + col) = v0;
            *reinterpret_cast<float2*>(out + (row0 + 8) * DD + col) = v1;
        }
    }
}

extern "C" void kernel_launch(void* const* d_in, const int* in_sizes, int n_in,
                              void* d_out, int out_size) {
    const float* x = (const float*)d_in[0];
    const float* W = (const float*)d_in[1];
    const float* V = (const float*)d_in[2];
    float* out = (float*)d_out;

    static bool attr_set = false;
    if (!attr_set) {
        cudaFuncSetAttribute(resnet_steps_kernel,
                             cudaFuncAttributeMaxDynamicSharedMemorySize, SMEM_BYTES);
        attr_set = true;
    }

    const long long batch = (long long)in_sizes[0] / DD;   // 2^21
    const int grid = (int)(batch / ROWS_PER_CTA);          // 4096, exact
    resnet_steps_kernel<<<grid, THREADS, SMEM_BYTES>>>(x, W, V, out);
}